// round 1
// baseline (speedup 1.0000x reference)
#include <cuda_runtime.h>
#include <cstdint>

// Fixed problem shapes (Gemma4VisionPooler): B=16, S=4096, D=1152, L=1024, k=2
#define BB 16
#define SS 4096
#define DD 1152
#define LL 1024
#define KK 2

// sqrt(1152) / k^2 = 33.9411255.../4
#define SCALE 8.4852813742385695f

// Scratch (no allocations allowed): per-batch (max_x+1)/k multiplier, per-cell counts
__device__ int g_mxk[BB];
__device__ int g_cnt[BB * LL];

// ---------------------------------------------------------------------------
// Kernel 1: zero the pooled output region + counts
// ---------------------------------------------------------------------------
__global__ void init_kernel(float4* __restrict__ out4) {
    const long n4 = (long)BB * LL * DD / 4;           // 4,718,592 float4
    const long stride = (long)gridDim.x * blockDim.x;
    float4 z = make_float4(0.f, 0.f, 0.f, 0.f);
    for (long i = (long)blockIdx.x * blockDim.x + threadIdx.x; i < n4; i += stride)
        out4[i] = z;
    for (long i = (long)blockIdx.x * blockDim.x + threadIdx.x; i < BB * LL; i += stride)
        g_cnt[i] = 0;
}

// ---------------------------------------------------------------------------
// Kernel 2: per-batch max over pos_x, store (max+1)/k
// ---------------------------------------------------------------------------
__global__ void max_kernel(const int* __restrict__ pos) {
    const int b = blockIdx.x;
    const int* p = pos + (long)b * SS * 2;
    int m = 0;
    for (int s = threadIdx.x; s < SS; s += blockDim.x) {
        int x = p[2 * s];
        if (x < 0) x = 0;
        m = max(m, x);
    }
    #pragma unroll
    for (int o = 16; o; o >>= 1) m = max(m, __shfl_xor_sync(0xffffffffu, m, o));
    __shared__ int sm[8];
    const int w = threadIdx.x >> 5;
    if ((threadIdx.x & 31) == 0) sm[w] = m;
    __syncthreads();
    if (threadIdx.x == 0) {
        int r = 0;
        for (int i = 0; i < (int)(blockDim.x >> 5); i++) r = max(r, sm[i]);
        g_mxk[b] = (r + 1) / KK;
    }
}

// ---------------------------------------------------------------------------
// Kernel 3: scatter. One warp per token. Each lane: 9x float4 load + 9x
// red.global.add.v4.f32 (fire-and-forget vector reduction at L2).
// ---------------------------------------------------------------------------
__device__ __forceinline__ void red_add_v4(float4* addr, float a, float b, float c, float d) {
    asm volatile("red.global.add.v4.f32 [%0], {%1, %2, %3, %4};"
                 :: "l"(addr), "f"(a), "f"(b), "f"(c), "f"(d) : "memory");
}

__global__ void __launch_bounds__(256) scatter_kernel(
    const float4* __restrict__ h4,
    const int* __restrict__ pos,
    const unsigned char* __restrict__ pad,
    float* __restrict__ out)
{
    const int warp = threadIdx.x >> 5;
    const int lane = threadIdx.x & 31;
    const long t = (long)blockIdx.x * 8 + warp;        // token index in [0, B*S)
    const int b = (int)(t >> 12);                      // t / 4096

    // All lanes read the same 3 scalars (broadcast in L1)
    int px = pos[2 * t];
    int py = pos[2 * t + 1];
    const int padded = pad[t];
    px = max(px, 0);
    py = max(py, 0);
    const int idx = (px / KK) + g_mxk[b] * (py / KK);
    if (idx < 0 || idx >= LL) return;                  // JAX drops OOB scatter indices

    if (lane == 0) atomicAdd(&g_cnt[b * LL + idx], 1); // counts include padded tokens
    if (padded) return;                                // padded tokens contribute zeros

    const float4* src = h4 + t * (DD / 4);
    float4* dst = (float4*)(out + ((long)b * LL + idx) * DD);

    float4 v[9];
    #pragma unroll
    for (int i = 0; i < 9; i++) v[i] = src[lane + 32 * i];  // MLP = 9, coalesced
    #pragma unroll
    for (int i = 0; i < 9; i++)
        red_add_v4(dst + lane + 32 * i,
                   v[i].x * SCALE, v[i].y * SCALE, v[i].z * SCALE, v[i].w * SCALE);
}

// ---------------------------------------------------------------------------
// Kernel 4: mask = (count > 0) as float 0/1, appended after pooled region
// ---------------------------------------------------------------------------
__global__ void mask_kernel(float* __restrict__ mask_out) {
    const int i = blockIdx.x * blockDim.x + threadIdx.x;
    if (i < BB * LL) mask_out[i] = (g_cnt[i] > 0) ? 1.0f : 0.0f;
}

// ---------------------------------------------------------------------------
extern "C" void kernel_launch(void* const* d_in, const int* in_sizes, int n_in,
                              void* d_out, int out_size) {
    const float4*        h   = (const float4*)d_in[0];
    const int*           pos = (const int*)d_in[1];
    const unsigned char* pad = (const unsigned char*)d_in[2];
    float* out = (float*)d_out;

    init_kernel<<<2048, 256>>>((float4*)out);
    max_kernel<<<BB, 256>>>(pos);
    scatter_kernel<<<(BB * SS) / 8, 256>>>(h, pos, pad, out);

    // If the harness expects the tuple's second output (mask), it follows the
    // pooled region: B*L*D floats, then B*L mask values.
    const long pooled_elems = (long)BB * LL * DD;
    if ((long)out_size >= pooled_elems + (long)BB * LL)
        mask_kernel<<<(BB * LL + 255) / 256, 256>>>(out + pooled_elems);
}

// round 2
// speedup vs baseline: 1.2893x; 1.2893x over previous
#include <cuda_runtime.h>
#include <cstdint>

// Fixed problem shapes (Gemma4VisionPooler): B=16, S=4096, D=1152, L=1024, k=2
#define BB 16
#define SS 4096
#define DD 1152
#define LL 1024
#define KK 2
#define D4 (DD / 4)          // 288 float4 per row

// sqrt(1152) / k^2
#define SCALE 8.4852813742385695f

// Scratch (no device allocations allowed)
__device__ int g_off[BB * LL];       // CSR start (global index into g_list)
__device__ int g_cnt[BB * LL];       // tokens per cell (incl. padded & zero)
__device__ int g_list[BB * SS];      // token id within batch; bit31 = padded

// ---------------------------------------------------------------------------
// Setup: one block per batch. max(pos_x) -> idx per token -> smem histogram
// -> smem scan -> CSR offsets -> fill token lists. Reads pos (2MB) + pad once.
// ---------------------------------------------------------------------------
__global__ void __launch_bounds__(1024) setup_kernel(
    const int* __restrict__ pos,
    const unsigned char* __restrict__ pad)
{
    const int b   = blockIdx.x;
    const int tid = threadIdx.x;
    const int* p  = pos + (long)b * SS * 2;

    __shared__ int sIdx[SS];     // per-token cell index (or -1 if dropped)
    __shared__ int sCnt[LL];     // histogram -> inclusive scan
    __shared__ int sCur[LL];     // fill cursors
    __shared__ int sMax[32];

    // ---- per-batch max over clamped pos_x ----
    int m = 0;
    for (int s = tid; s < SS; s += 1024) {
        int x = p[2 * s];
        m = max(m, max(x, 0));
    }
    #pragma unroll
    for (int o = 16; o; o >>= 1) m = max(m, __shfl_xor_sync(0xffffffffu, m, o));
    if ((tid & 31) == 0) sMax[tid >> 5] = m;
    __syncthreads();
    if (tid < 32) {
        int r = sMax[tid];
        #pragma unroll
        for (int o = 16; o; o >>= 1) r = max(r, __shfl_xor_sync(0xffffffffu, r, o));
        if (tid == 0) sMax[0] = (r + 1) / KK;
    }
    if (tid < LL) sCnt[tid] = 0;
    __syncthreads();
    const int mxk = sMax[0];

    // ---- idx per token + histogram ----
    #pragma unroll
    for (int it = 0; it < SS / 1024; it++) {
        const int s = tid + it * 1024;
        int px = max(p[2 * s], 0);
        int py = max(p[2 * s + 1], 0);
        int idx = (px / KK) + mxk * (py / KK);
        if (idx >= 0 && idx < LL) {
            atomicAdd(&sCnt[idx], 1);
        } else {
            idx = -1;                              // OOB scatter index: dropped
        }
        sIdx[s] = idx;
    }
    __syncthreads();

    // ---- inclusive scan over 1024 counters (first 1024 threads) ----
    #pragma unroll
    for (int off = 1; off < LL; off <<= 1) {
        int t = (tid < LL && tid >= off) ? sCnt[tid - off] : 0;
        __syncthreads();
        if (tid < LL) sCnt[tid] += t;
        __syncthreads();
    }

    // ---- write CSR offsets/counts, init cursors ----
    if (tid < LL) {
        const int incl = sCnt[tid];
        const int excl = (tid == 0) ? 0 : sCnt[tid - 1];
        const int cell = b * LL + tid;
        g_off[cell] = b * SS + excl;
        g_cnt[cell] = incl - excl;
        sCur[tid]   = excl;
    }
    __syncthreads();

    // ---- fill token lists ----
    const unsigned char* pb = pad + (long)b * SS;
    #pragma unroll
    for (int it = 0; it < SS / 1024; it++) {
        const int s = tid + it * 1024;
        const int idx = sIdx[s];
        if (idx >= 0) {
            const int slot = atomicAdd(&sCur[idx], 1);
            g_list[b * SS + slot] = s | (pb[s] ? 0x80000000 : 0);
        }
    }
}

// ---------------------------------------------------------------------------
// Gather: one block per output cell (16384 blocks). 288 threads = one float4
// column each. Sum cnt rows (skip padded), write once. No init, no atomics.
// ---------------------------------------------------------------------------
__global__ void __launch_bounds__(D4) gather_kernel(
    const float4* __restrict__ h4,
    float4* __restrict__ out4,
    float* __restrict__ mask_out,     // nullptr if not requested
    int write_mask)
{
    const int cell  = blockIdx.x;
    const int tid   = threadIdx.x;
    const int start = g_off[cell];
    const int cnt   = g_cnt[cell];
    const float4* hb = h4 + (long)(cell >> 10) * SS * D4;   // batch base

    float4 acc = make_float4(0.f, 0.f, 0.f, 0.f);

    int j = 0;
    // 2-token unroll: two independent row loads in flight per thread
    for (; j + 2 <= cnt; j += 2) {
        const int e0 = g_list[start + j];
        const int e1 = g_list[start + j + 1];
        float4 v0 = make_float4(0.f, 0.f, 0.f, 0.f);
        float4 v1 = make_float4(0.f, 0.f, 0.f, 0.f);
        if (e0 >= 0) v0 = hb[(long)e0 * D4 + tid];
        if (e1 >= 0) v1 = hb[(long)e1 * D4 + tid];
        acc.x += v0.x + v1.x;
        acc.y += v0.y + v1.y;
        acc.z += v0.z + v1.z;
        acc.w += v0.w + v1.w;
    }
    if (j < cnt) {
        const int e = g_list[start + j];
        if (e >= 0) {
            const float4 v = hb[(long)e * D4 + tid];
            acc.x += v.x; acc.y += v.y; acc.z += v.z; acc.w += v.w;
        }
    }

    acc.x *= SCALE; acc.y *= SCALE; acc.z *= SCALE; acc.w *= SCALE;
    out4[(long)cell * D4 + tid] = acc;

    if (write_mask && tid == 0)
        mask_out[cell] = (cnt > 0) ? 1.0f : 0.0f;
}

// ---------------------------------------------------------------------------
extern "C" void kernel_launch(void* const* d_in, const int* in_sizes, int n_in,
                              void* d_out, int out_size) {
    const float4*        h   = (const float4*)d_in[0];
    const int*           pos = (const int*)d_in[1];
    const unsigned char* pad = (const unsigned char*)d_in[2];
    float* out = (float*)d_out;

    const long pooled_elems = (long)BB * LL * DD;
    const int  want_mask    = ((long)out_size >= pooled_elems + (long)BB * LL) ? 1 : 0;
    float* mask_out = want_mask ? (out + pooled_elems) : nullptr;

    setup_kernel<<<BB, 1024>>>(pos, pad);
    gather_kernel<<<BB * LL, D4>>>(h, (float4*)out, mask_out, want_mask);
}